// round 3
// baseline (speedup 1.0000x reference)
#include <cuda_runtime.h>
#include <math_constants.h>
#include <cfloat>

// ---------------------------------------------------------------------------
// SparseEventNet: segment mean+max pool (N rows, C=128, sorted batch ids)
// followed by a tiny MLP head (2C -> 128 -> 64 -> 32 -> 4).
// HBM-bound: 1.024 GB feature stream read exactly once.
// R3: no init kernel (zero-identity max encoding + head-side scratch reset),
//     single-wave grid (592 blocks = 4/SM x 148 SMs).
// ---------------------------------------------------------------------------

#define C_CH 128
#define B_MAX 1024

// Scratch (no cudaMalloc allowed). Module load zero-initializes these, and
// head_kernel restores them to all-zero after consuming them, so every call
// to kernel_launch sees identical (zeroed) scratch. Zero is the identity for
// all three accumulators (sum, offset-encoded max, count).
__device__ float    g_sum[B_MAX * C_CH];
__device__ unsigned g_maxk[B_MAX * C_CH];
__device__ float    g_cnt[B_MAX];

// Monotonic float->uint mapping, offset so that 0 == identity (-FLT_MAX).
__device__ __forceinline__ unsigned f2k_raw(float f) {
    unsigned b = __float_as_uint(f);
    return (b & 0x80000000u) ? ~b : (b | 0x80000000u);
}
// f2k_raw(-FLT_MAX) = ~0xFF7FFFFF = 0x00800000
#define MAXK_BIAS 0x00800000u
__device__ __forceinline__ unsigned f2k(float f) {
    unsigned k = f2k_raw(f);
    return (k <= MAXK_BIAS) ? 0u : (k - MAXK_BIAS);
}
__device__ __forceinline__ float k2f(unsigned k) {
    unsigned raw = k + MAXK_BIAS;
    unsigned b = (raw & 0x80000000u) ? (raw & 0x7FFFFFFFu) : ~raw;
    return __uint_as_float(b);
}

// ---------------------------------------------------------------------------
// Segment reduce: one warp owns a contiguous row range. Lane l holds channels
// [4l, 4l+4) in registers (float4). Flush to global atomics only on segment
// change / range end. 8-row unroll, endpoint bids check (ids are sorted).
// ---------------------------------------------------------------------------
__global__ void __launch_bounds__(256) reduce_kernel(
    const float4* __restrict__ feat,   // [N, 32] float4 view of [N, 128]
    const int*    __restrict__ bids,   // [N], sorted
    int N, int rows_per_warp)
{
    const int gw   = (blockIdx.x * blockDim.x + threadIdx.x) >> 5;
    const int lane = threadIdx.x & 31;

    int r    = gw * rows_per_warp;
    if (r >= N) return;
    int rend = min(N, r + rows_per_warp);

    int    cur = bids[r];
    float4 s   = make_float4(0.f, 0.f, 0.f, 0.f);
    float4 m   = make_float4(-CUDART_INF_F, -CUDART_INF_F, -CUDART_INF_F, -CUDART_INF_F);
    int    cnt = 0;

#define ACC(v)                                                \
    do {                                                      \
        s.x += (v).x; s.y += (v).y;                           \
        s.z += (v).z; s.w += (v).w;                           \
        m.x = fmaxf(m.x, (v).x); m.y = fmaxf(m.y, (v).y);     \
        m.z = fmaxf(m.z, (v).z); m.w = fmaxf(m.w, (v).w);     \
    } while (0)

#define FLUSH()                                                              \
    do {                                                                     \
        if (cnt > 0) {                                                       \
            float*    sp = &g_sum [cur * C_CH + lane * 4];                   \
            unsigned* mp = &g_maxk[cur * C_CH + lane * 4];                   \
            atomicAdd(sp + 0, s.x); atomicAdd(sp + 1, s.y);                  \
            atomicAdd(sp + 2, s.z); atomicAdd(sp + 3, s.w);                  \
            atomicMax(mp + 0, f2k(m.x)); atomicMax(mp + 1, f2k(m.y));        \
            atomicMax(mp + 2, f2k(m.z)); atomicMax(mp + 3, f2k(m.w));        \
            if (lane == 0) atomicAdd(&g_cnt[cur], (float)cnt);               \
        }                                                                    \
    } while (0)

#define STEP(b, v)                                                           \
    do {                                                                     \
        if ((b) != cur) {                                                    \
            FLUSH();                                                         \
            cur = (b);                                                       \
            s = make_float4(0.f, 0.f, 0.f, 0.f);                             \
            m = make_float4(-CUDART_INF_F, -CUDART_INF_F,                    \
                            -CUDART_INF_F, -CUDART_INF_F);                   \
            cnt = 0;                                                         \
        }                                                                    \
        ACC(v);                                                              \
        cnt++;                                                               \
    } while (0)

    // 8-row unrolled main loop: 8 front-batched streaming LDG.128 per thread.
    while (r + 8 <= rend) {
        // sorted ids: if both endpoints match cur, all 8 rows are interior.
        int b0 = bids[r];
        int b7 = bids[r + 7];
        const float4* p = feat + (size_t)r * 32 + lane;
        float4 v0 = __ldcs(p +   0);
        float4 v1 = __ldcs(p +  32);
        float4 v2 = __ldcs(p +  64);
        float4 v3 = __ldcs(p +  96);
        float4 v4 = __ldcs(p + 128);
        float4 v5 = __ldcs(p + 160);
        float4 v6 = __ldcs(p + 192);
        float4 v7 = __ldcs(p + 224);
        if (b0 == cur && b7 == cur) {
            ACC(v0); ACC(v1); ACC(v2); ACC(v3);
            ACC(v4); ACC(v5); ACC(v6); ACC(v7);
            cnt += 8;
        } else {
            int a1 = bids[r + 1], a2 = bids[r + 2], a3 = bids[r + 3];
            int a4 = bids[r + 4], a5 = bids[r + 5], a6 = bids[r + 6];
            STEP(b0, v0); STEP(a1, v1); STEP(a2, v2); STEP(a3, v3);
            STEP(a4, v4); STEP(a5, v5); STEP(a6, v6); STEP(b7, v7);
        }
        r += 8;
    }
    while (r < rend) {
        int    a = bids[r];
        float4 v = __ldcs(feat + (size_t)r * 32 + lane);
        STEP(a, v);
        r++;
    }
    FLUSH();

#undef STEP
#undef FLUSH
#undef ACC
}

// ---------------------------------------------------------------------------
// Finalize pooling + MLP head + scratch reset. One block (128 threads) per
// batch element. pooled = [mean(128) | max(128)]; empty segments -> zeros.
// After consuming the accumulators this kernel zeroes them again so the next
// kernel_launch call starts from the same state (graph-replay invariant).
// ---------------------------------------------------------------------------
__global__ void __launch_bounds__(128) head_kernel(
    const float* __restrict__ W1, const float* __restrict__ b1,   // [256,128],[128]
    const float* __restrict__ W2, const float* __restrict__ b2,   // [128, 64],[ 64]
    const float* __restrict__ W3, const float* __restrict__ b3,   // [ 64, 32],[ 32]
    const float* __restrict__ W4, const float* __restrict__ b4,   // [ 32,  4],[  4]
    float* __restrict__ out)                                      // [B, 4]
{
    const int b = blockIdx.x;
    const int t = threadIdx.x;

    __shared__ float pooled[2 * C_CH];
    __shared__ float h1[128];
    __shared__ float h2[64];
    __shared__ float h3[32];

    float cnt = g_cnt[b];
    bool  ne  = cnt > 0.0f;
    float sum = g_sum[b * C_CH + t];
    float mx  = k2f(g_maxk[b * C_CH + t]);
    pooled[t]        = ne ? (sum / cnt) : 0.0f;
    pooled[C_CH + t] = ne ? mx : 0.0f;

    // Reset scratch to the all-zero identity state for the next call.
    g_sum [b * C_CH + t] = 0.0f;
    g_maxk[b * C_CH + t] = 0u;
    if (t == 0) g_cnt[b] = 0.0f;
    __syncthreads();

    // Layer 1: [256] -> [128]
    {
        float acc = b1[t];
#pragma unroll 8
        for (int i = 0; i < 2 * C_CH; i++) acc += pooled[i] * W1[i * 128 + t];
        h1[t] = fmaxf(acc, 0.0f);
    }
    __syncthreads();

    // Layer 2: [128] -> [64]
    if (t < 64) {
        float acc = b2[t];
#pragma unroll 8
        for (int i = 0; i < 128; i++) acc += h1[i] * W2[i * 64 + t];
        h2[t] = fmaxf(acc, 0.0f);
    }
    __syncthreads();

    // Layer 3: [64] -> [32]
    if (t < 32) {
        float acc = b3[t];
#pragma unroll 8
        for (int i = 0; i < 64; i++) acc += h2[i] * W3[i * 32 + t];
        h3[t] = fmaxf(acc, 0.0f);
    }
    __syncthreads();

    // Layer 4: [32] -> [4]
    if (t < 4) {
        float acc = b4[t];
#pragma unroll
        for (int i = 0; i < 32; i++) acc += h3[i] * W4[i * 4 + t];
        out[b * 4 + t] = acc;
    }
}

// ---------------------------------------------------------------------------
extern "C" void kernel_launch(void* const* d_in, const int* in_sizes, int n_in,
                              void* d_out, int out_size)
{
    const float* feat = (const float*)d_in[0];
    const int*   bids = (const int*)d_in[1];

    // Inputs (metadata order): features, batch_ids, [batch_size scalar?],
    // W1,b1,W2,b2,W3,b3,W4,b4. Detect whether the scalar batch_size is present.
    int wbase = 2;
    if (n_in >= 11 && in_sizes[2] == 1) wbase = 3;  // skip scalar batch_size

    const float* W1 = (const float*)d_in[wbase + 0];
    const float* b1 = (const float*)d_in[wbase + 1];
    const float* W2 = (const float*)d_in[wbase + 2];
    const float* b2 = (const float*)d_in[wbase + 3];
    const float* W3 = (const float*)d_in[wbase + 4];
    const float* b3 = (const float*)d_in[wbase + 5];
    const float* W4 = (const float*)d_in[wbase + 6];
    const float* b4 = (const float*)d_in[wbase + 7];

    const int N = in_sizes[0] / C_CH;     // rows
    const int B = out_size / 4;           // batch size from output shape

    // 1) segment reduce: single resident wave.
    //    ~60 regs/thread -> 4 blocks/SM at 256 threads; 4 x 148 = 592 blocks.
    {
        int blocks  = 592;
        int threads = 256;
        int total_warps = blocks * (threads / 32);     // 4736
        int rpw = (N + total_warps - 1) / total_warps;
        rpw = (rpw + 7) & ~7;   // multiple of 8 so the unrolled loop dominates
        reduce_kernel<<<blocks, threads>>>((const float4*)feat, bids, N, rpw);
    }

    // 2) finalize + MLP head + scratch reset
    head_kernel<<<B, 128>>>(W1, b1, W2, b2, W3, b3, W4, b4, (float*)d_out);
}

// round 4
// speedup vs baseline: 1.0258x; 1.0258x over previous
#include <cuda_runtime.h>
#include <math_constants.h>
#include <cfloat>

// ---------------------------------------------------------------------------
// SparseEventNet: segment mean+max pool (N rows, C=128, sorted batch ids)
// followed by a tiny MLP head (2C -> 128 -> 64 -> 32 -> 4).
// HBM-bound: 1.024 GB feature stream read exactly once.
// R4: revert reduce grid to 1184 blocks (2 waves self-smooth the straggler
//     spread); batch-tiled head (8 batches/block, W1 staged via smem) to kill
//     the 31.6us latency-bound head.
// ---------------------------------------------------------------------------

#define C_CH 128
#define B_MAX 1024
#define TB    8      // batches per head block

// Scratch (no cudaMalloc allowed). Module load zero-initializes these, and
// head_kernel restores them to all-zero after consuming them, so every call
// to kernel_launch sees identical (zeroed) scratch. Zero is the identity for
// all three accumulators (sum, offset-encoded max, count).
__device__ float    g_sum[B_MAX * C_CH];
__device__ unsigned g_maxk[B_MAX * C_CH];
__device__ float    g_cnt[B_MAX];

// Monotonic float->uint mapping, offset so that 0 == identity (-FLT_MAX).
__device__ __forceinline__ unsigned f2k_raw(float f) {
    unsigned b = __float_as_uint(f);
    return (b & 0x80000000u) ? ~b : (b | 0x80000000u);
}
// f2k_raw(-FLT_MAX) = ~0xFF7FFFFF = 0x00800000
#define MAXK_BIAS 0x00800000u
__device__ __forceinline__ unsigned f2k(float f) {
    unsigned k = f2k_raw(f);
    return (k <= MAXK_BIAS) ? 0u : (k - MAXK_BIAS);
}
__device__ __forceinline__ float k2f(unsigned k) {
    unsigned raw = k + MAXK_BIAS;
    unsigned b = (raw & 0x80000000u) ? (raw & 0x7FFFFFFFu) : ~raw;
    return __uint_as_float(b);
}

// ---------------------------------------------------------------------------
// Segment reduce: one warp owns a contiguous row range. Lane l holds channels
// [4l, 4l+4) in registers (float4). Flush to global atomics only on segment
// change / range end. 8-row unroll, endpoint bids check (ids are sorted).
// ---------------------------------------------------------------------------
__global__ void __launch_bounds__(256) reduce_kernel(
    const float4* __restrict__ feat,   // [N, 32] float4 view of [N, 128]
    const int*    __restrict__ bids,   // [N], sorted
    int N, int rows_per_warp)
{
    const int gw   = (blockIdx.x * blockDim.x + threadIdx.x) >> 5;
    const int lane = threadIdx.x & 31;

    int r    = gw * rows_per_warp;
    if (r >= N) return;
    int rend = min(N, r + rows_per_warp);

    int    cur = bids[r];
    float4 s   = make_float4(0.f, 0.f, 0.f, 0.f);
    float4 m   = make_float4(-CUDART_INF_F, -CUDART_INF_F, -CUDART_INF_F, -CUDART_INF_F);
    int    cnt = 0;

#define ACC(v)                                                \
    do {                                                      \
        s.x += (v).x; s.y += (v).y;                           \
        s.z += (v).z; s.w += (v).w;                           \
        m.x = fmaxf(m.x, (v).x); m.y = fmaxf(m.y, (v).y);     \
        m.z = fmaxf(m.z, (v).z); m.w = fmaxf(m.w, (v).w);     \
    } while (0)

#define FLUSH()                                                              \
    do {                                                                     \
        if (cnt > 0) {                                                       \
            float*    sp = &g_sum [cur * C_CH + lane * 4];                   \
            unsigned* mp = &g_maxk[cur * C_CH + lane * 4];                   \
            atomicAdd(sp + 0, s.x); atomicAdd(sp + 1, s.y);                  \
            atomicAdd(sp + 2, s.z); atomicAdd(sp + 3, s.w);                  \
            atomicMax(mp + 0, f2k(m.x)); atomicMax(mp + 1, f2k(m.y));        \
            atomicMax(mp + 2, f2k(m.z)); atomicMax(mp + 3, f2k(m.w));        \
            if (lane == 0) atomicAdd(&g_cnt[cur], (float)cnt);               \
        }                                                                    \
    } while (0)

#define STEP(b, v)                                                           \
    do {                                                                     \
        if ((b) != cur) {                                                    \
            FLUSH();                                                         \
            cur = (b);                                                       \
            s = make_float4(0.f, 0.f, 0.f, 0.f);                             \
            m = make_float4(-CUDART_INF_F, -CUDART_INF_F,                    \
                            -CUDART_INF_F, -CUDART_INF_F);                   \
            cnt = 0;                                                         \
        }                                                                    \
        ACC(v);                                                              \
        cnt++;                                                               \
    } while (0)

    // 8-row unrolled main loop: 8 front-batched streaming LDG.128 per thread.
    while (r + 8 <= rend) {
        // sorted ids: if both endpoints match cur, all 8 rows are interior.
        int b0 = bids[r];
        int b7 = bids[r + 7];
        const float4* p = feat + (size_t)r * 32 + lane;
        float4 v0 = __ldcs(p +   0);
        float4 v1 = __ldcs(p +  32);
        float4 v2 = __ldcs(p +  64);
        float4 v3 = __ldcs(p +  96);
        float4 v4 = __ldcs(p + 128);
        float4 v5 = __ldcs(p + 160);
        float4 v6 = __ldcs(p + 192);
        float4 v7 = __ldcs(p + 224);
        if (b0 == cur && b7 == cur) {
            ACC(v0); ACC(v1); ACC(v2); ACC(v3);
            ACC(v4); ACC(v5); ACC(v6); ACC(v7);
            cnt += 8;
        } else {
            int a1 = bids[r + 1], a2 = bids[r + 2], a3 = bids[r + 3];
            int a4 = bids[r + 4], a5 = bids[r + 5], a6 = bids[r + 6];
            STEP(b0, v0); STEP(a1, v1); STEP(a2, v2); STEP(a3, v3);
            STEP(a4, v4); STEP(a5, v5); STEP(a6, v6); STEP(b7, v7);
        }
        r += 8;
    }
    while (r < rend) {
        int    a = bids[r];
        float4 v = __ldcs(feat + (size_t)r * 32 + lane);
        STEP(a, v);
        r++;
    }
    FLUSH();

#undef STEP
#undef FLUSH
#undef ACC
}

// ---------------------------------------------------------------------------
// Finalize pooling + MLP head + scratch reset. One block (128 threads) per
// TB=8 batches. Layer 1 stages W1 through smem in 32-row chunks so each block
// reads W1 exactly once (coalesced float4), amortized across 8 batches.
// After consuming the accumulators this kernel zeroes them (graph-replay
// invariant: scratch is all-zero before every kernel_launch call).
// ---------------------------------------------------------------------------
__global__ void __launch_bounds__(128) head_kernel(
    const float* __restrict__ W1, const float* __restrict__ b1,   // [256,128],[128]
    const float* __restrict__ W2, const float* __restrict__ b2,   // [128, 64],[ 64]
    const float* __restrict__ W3, const float* __restrict__ b3,   // [ 64, 32],[ 32]
    const float* __restrict__ W4, const float* __restrict__ b4,   // [ 32,  4],[  4]
    float* __restrict__ out, int B)                               // [B, 4]
{
    const int b0 = blockIdx.x * TB;
    const int t  = threadIdx.x;

    __shared__ float pooled_s[TB][2 * C_CH];  // 8 KB
    __shared__ float w_s[32][128];            // 16 KB (W1 chunk)
    __shared__ float h1_s[TB][128];           // 4 KB
    __shared__ float h2_s[TB][64];            // 2 KB
    __shared__ float h3_s[TB][32];            // 1 KB

    // ---- finalize pooling for TB batches, reset scratch ----
#pragma unroll
    for (int i = 0; i < TB; i++) {
        int b = b0 + i;
        if (b < B) {
            float cnt = g_cnt[b];
            bool  ne  = cnt > 0.0f;
            float sum = g_sum[b * C_CH + t];
            float mx  = k2f(g_maxk[b * C_CH + t]);
            pooled_s[i][t]        = ne ? (sum / cnt) : 0.0f;
            pooled_s[i][C_CH + t] = ne ? mx : 0.0f;
            g_sum [b * C_CH + t] = 0.0f;
            g_maxk[b * C_CH + t] = 0u;
            if (t == 0) g_cnt[b] = 0.0f;
        } else {
            pooled_s[i][t]        = 0.0f;
            pooled_s[i][C_CH + t] = 0.0f;
        }
    }

    // ---- Layer 1: [256] -> [128], thread t owns output channel t for all
    //      TB batches; W1 staged through smem in 32-row chunks ----
    float acc[TB];
#pragma unroll
    for (int i = 0; i < TB; i++) acc[i] = b1[t];

    for (int k0 = 0; k0 < 2 * C_CH; k0 += 32) {
        __syncthreads();   // also covers pooled_s on first iter, w_s reuse after
        // cooperative load of 32x128 chunk = 1024 float4, 8 per thread
        const float4* src = (const float4*)(W1 + k0 * 128);
        float4*       dst = (float4*)w_s;
#pragma unroll
        for (int j = 0; j < 8; j++) dst[t + j * 128] = src[t + j * 128];
        __syncthreads();
#pragma unroll
        for (int k = 0; k < 32; k++) {
            float w = w_s[k][t];
#pragma unroll
            for (int i = 0; i < TB; i++)
                acc[i] += pooled_s[i][k0 + k] * w;
        }
    }
#pragma unroll
    for (int i = 0; i < TB; i++) h1_s[i][t] = fmaxf(acc[i], 0.0f);
    __syncthreads();

    // ---- Layer 2: [128] -> [64]; t -> (out o = t&63, batch half t>>6) ----
    {
        const int o    = t & 63;
        const int half = t >> 6;          // 0 or 1 -> batches half*4 .. +3
        float a2[4];
#pragma unroll
        for (int j = 0; j < 4; j++) a2[j] = b2[o];
#pragma unroll 4
        for (int k = 0; k < 128; k++) {
            float w = W2[k * 64 + o];
#pragma unroll
            for (int j = 0; j < 4; j++) a2[j] += h1_s[half * 4 + j][k] * w;
        }
#pragma unroll
        for (int j = 0; j < 4; j++)
            h2_s[half * 4 + j][o] = fmaxf(a2[j], 0.0f);
    }
    __syncthreads();

    // ---- Layer 3: [64] -> [32]; t -> (out o = t&31, batch pair t>>5) ----
    {
        const int o = t & 31;
        const int q = t >> 5;             // 0..3 -> batches q*2, q*2+1
        float a3[2];
        a3[0] = b3[o]; a3[1] = b3[o];
#pragma unroll 4
        for (int k = 0; k < 64; k++) {
            float w = W3[k * 32 + o];
            a3[0] += h2_s[q * 2 + 0][k] * w;
            a3[1] += h2_s[q * 2 + 1][k] * w;
        }
        h3_s[q * 2 + 0][o] = fmaxf(a3[0], 0.0f);
        h3_s[q * 2 + 1][o] = fmaxf(a3[1], 0.0f);
    }
    __syncthreads();

    // ---- Layer 4: [32] -> [4]; threads 0..31: (out o = t&3, batch t>>2) ----
    if (t < 32) {
        const int o = t & 3;
        const int i = t >> 2;
        float a4 = b4[o];
#pragma unroll
        for (int k = 0; k < 32; k++) a4 += h3_s[i][k] * W4[k * 4 + o];
        int b = b0 + i;
        if (b < B) out[b * 4 + o] = a4;
    }
}

// ---------------------------------------------------------------------------
extern "C" void kernel_launch(void* const* d_in, const int* in_sizes, int n_in,
                              void* d_out, int out_size)
{
    const float* feat = (const float*)d_in[0];
    const int*   bids = (const int*)d_in[1];

    // Inputs (metadata order): features, batch_ids, [batch_size scalar?],
    // W1,b1,W2,b2,W3,b3,W4,b4. Detect whether the scalar batch_size is present.
    int wbase = 2;
    if (n_in >= 11 && in_sizes[2] == 1) wbase = 3;  // skip scalar batch_size

    const float* W1 = (const float*)d_in[wbase + 0];
    const float* b1 = (const float*)d_in[wbase + 1];
    const float* W2 = (const float*)d_in[wbase + 2];
    const float* b2 = (const float*)d_in[wbase + 3];
    const float* W3 = (const float*)d_in[wbase + 4];
    const float* b3 = (const float*)d_in[wbase + 5];
    const float* W4 = (const float*)d_in[wbase + 6];
    const float* b4 = (const float*)d_in[wbase + 7];

    const int N = in_sizes[0] / C_CH;     // rows
    const int B = out_size / 4;           // batch size from output shape

    // 1) segment reduce: 1184 blocks x 8 warps = 9472 warps (2 waves; the
    //    second wave smooths straggler spread better than one big wave).
    {
        int blocks  = 1184;
        int threads = 256;
        int total_warps = blocks * (threads / 32);
        int rpw = (N + total_warps - 1) / total_warps;
        rpw = (rpw + 7) & ~7;   // multiple of 8 so the unrolled loop dominates
        reduce_kernel<<<blocks, threads>>>((const float4*)feat, bids, N, rpw);
    }

    // 2) finalize + MLP head + scratch reset: 8 batches per block
    {
        int blocks = (B + TB - 1) / TB;
        head_kernel<<<blocks, 128>>>(W1, b1, W2, b2, W3, b3, W4, b4,
                                     (float*)d_out, B);
    }
}

// round 6
// speedup vs baseline: 1.0967x; 1.0690x over previous
#include <cuda_runtime.h>
#include <math_constants.h>
#include <cfloat>

// ---------------------------------------------------------------------------
// SparseEventNet: segment mean+max pool (N rows, C=128, sorted batch ids)
// followed by a tiny MLP head (2C -> 128 -> 64 -> 32 -> 4).
// Reduce (R2-validated) runs at ~7.9 TB/s. R6: head rebuilt as a provable
// split-K design: 128 blocks x 256 threads, TB=2 batches/block, direct
// coalesced LDG weights (no smem staging), write-once partial buffers,
// unconditional barriers.
// ---------------------------------------------------------------------------

#define C_CH 128
#define B_MAX 1024
#define TB    2      // batches per head block

// Scratch (no cudaMalloc allowed). Module load zero-initializes these, and
// head_kernel restores them to all-zero after consuming them, so every call
// to kernel_launch sees identical (zeroed) scratch. Zero is the identity for
// all three accumulators (sum, offset-encoded max, count).
__device__ float    g_sum[B_MAX * C_CH];
__device__ unsigned g_maxk[B_MAX * C_CH];
__device__ float    g_cnt[B_MAX];

// Monotonic float->uint mapping, offset so that 0 == identity (-FLT_MAX).
__device__ __forceinline__ unsigned f2k_raw(float f) {
    unsigned b = __float_as_uint(f);
    return (b & 0x80000000u) ? ~b : (b | 0x80000000u);
}
// f2k_raw(-FLT_MAX) = ~0xFF7FFFFF = 0x00800000
#define MAXK_BIAS 0x00800000u
__device__ __forceinline__ unsigned f2k(float f) {
    unsigned k = f2k_raw(f);
    return (k <= MAXK_BIAS) ? 0u : (k - MAXK_BIAS);
}
__device__ __forceinline__ float k2f(unsigned k) {
    unsigned raw = k + MAXK_BIAS;
    unsigned b = (raw & 0x80000000u) ? (raw & 0x7FFFFFFFu) : ~raw;
    return __uint_as_float(b);
}

// ---------------------------------------------------------------------------
// Segment reduce: one warp owns a contiguous row range. Lane l holds channels
// [4l, 4l+4) in registers (float4). Flush to global atomics only on segment
// change / range end. 8-row unroll, endpoint bids check (ids are sorted).
// (Unchanged from R2/R4 — validated at ~7.9 TB/s.)
// ---------------------------------------------------------------------------
__global__ void __launch_bounds__(256) reduce_kernel(
    const float4* __restrict__ feat,   // [N, 32] float4 view of [N, 128]
    const int*    __restrict__ bids,   // [N], sorted
    int N, int rows_per_warp)
{
    const int gw   = (blockIdx.x * blockDim.x + threadIdx.x) >> 5;
    const int lane = threadIdx.x & 31;

    int r    = gw * rows_per_warp;
    if (r >= N) return;
    int rend = min(N, r + rows_per_warp);

    int    cur = bids[r];
    float4 s   = make_float4(0.f, 0.f, 0.f, 0.f);
    float4 m   = make_float4(-CUDART_INF_F, -CUDART_INF_F, -CUDART_INF_F, -CUDART_INF_F);
    int    cnt = 0;

#define ACC(v)                                                \
    do {                                                      \
        s.x += (v).x; s.y += (v).y;                           \
        s.z += (v).z; s.w += (v).w;                           \
        m.x = fmaxf(m.x, (v).x); m.y = fmaxf(m.y, (v).y);     \
        m.z = fmaxf(m.z, (v).z); m.w = fmaxf(m.w, (v).w);     \
    } while (0)

#define FLUSH()                                                              \
    do {                                                                     \
        if (cnt > 0) {                                                       \
            float*    sp = &g_sum [cur * C_CH + lane * 4];                   \
            unsigned* mp = &g_maxk[cur * C_CH + lane * 4];                   \
            atomicAdd(sp + 0, s.x); atomicAdd(sp + 1, s.y);                  \
            atomicAdd(sp + 2, s.z); atomicAdd(sp + 3, s.w);                  \
            atomicMax(mp + 0, f2k(m.x)); atomicMax(mp + 1, f2k(m.y));        \
            atomicMax(mp + 2, f2k(m.z)); atomicMax(mp + 3, f2k(m.w));        \
            if (lane == 0) atomicAdd(&g_cnt[cur], (float)cnt);               \
        }                                                                    \
    } while (0)

#define STEP(b, v)                                                           \
    do {                                                                     \
        if ((b) != cur) {                                                    \
            FLUSH();                                                         \
            cur = (b);                                                       \
            s = make_float4(0.f, 0.f, 0.f, 0.f);                             \
            m = make_float4(-CUDART_INF_F, -CUDART_INF_F,                    \
                            -CUDART_INF_F, -CUDART_INF_F);                   \
            cnt = 0;                                                         \
        }                                                                    \
        ACC(v);                                                              \
        cnt++;                                                               \
    } while (0)

    while (r + 8 <= rend) {
        int b0 = bids[r];
        int b7 = bids[r + 7];
        const float4* p = feat + (size_t)r * 32 + lane;
        float4 v0 = __ldcs(p +   0);
        float4 v1 = __ldcs(p +  32);
        float4 v2 = __ldcs(p +  64);
        float4 v3 = __ldcs(p +  96);
        float4 v4 = __ldcs(p + 128);
        float4 v5 = __ldcs(p + 160);
        float4 v6 = __ldcs(p + 192);
        float4 v7 = __ldcs(p + 224);
        if (b0 == cur && b7 == cur) {
            ACC(v0); ACC(v1); ACC(v2); ACC(v3);
            ACC(v4); ACC(v5); ACC(v6); ACC(v7);
            cnt += 8;
        } else {
            int a1 = bids[r + 1], a2 = bids[r + 2], a3 = bids[r + 3];
            int a4 = bids[r + 4], a5 = bids[r + 5], a6 = bids[r + 6];
            STEP(b0, v0); STEP(a1, v1); STEP(a2, v2); STEP(a3, v3);
            STEP(a4, v4); STEP(a5, v5); STEP(a6, v6); STEP(b7, v7);
        }
        r += 8;
    }
    while (r < rend) {
        int    a = bids[r];
        float4 v = __ldcs(feat + (size_t)r * 32 + lane);
        STEP(a, v);
        r++;
    }
    FLUSH();

#undef STEP
#undef FLUSH
#undef ACC
}

// ---------------------------------------------------------------------------
// Head: finalize pooling + MLP + scratch reset.
// 256 threads per block, TB=2 batches per block, grid = ceil(B/2) = 128.
// Split-K per layer; every smem array is written once and read once, with an
// unconditional __syncthreads() between. All weight reads are coalesced LDG.
// ---------------------------------------------------------------------------
__global__ void __launch_bounds__(256) head_kernel(
    const float* __restrict__ W1, const float* __restrict__ b1,   // [256,128],[128]
    const float* __restrict__ W2, const float* __restrict__ b2,   // [128, 64],[ 64]
    const float* __restrict__ W3, const float* __restrict__ b3,   // [ 64, 32],[ 32]
    const float* __restrict__ W4, const float* __restrict__ b4,   // [ 32,  4],[  4]
    float* __restrict__ out, int B)                               // [B, 4]
{
    const int blk_b0 = blockIdx.x * TB;
    const int t      = threadIdx.x;

    __shared__ float pooled_s[TB][2 * C_CH];   // 2 KB   written step A
    __shared__ float p1_s[2][TB][128];         // 2 KB   layer-1 partials
    __shared__ float h1_s[TB][128];            // 1 KB
    __shared__ float p2_s[2][TB][64];          // 1 KB   layer-2 partials
    __shared__ float h2_s[TB][64];             // 0.5 KB
    __shared__ float p3_s[4][TB][32];          // 1 KB   layer-3 partials
    __shared__ float h3_s[TB][32];             // 0.25 KB

    // ---- Step A: finalize pooling (256 threads = 2 batches x 128 ch) ----
    {
        const int i = t >> 7;         // batch slot 0..1
        const int c = t & 127;        // channel
        const int b = blk_b0 + i;
        if (b < B) {
            float cnt = g_cnt[b];
            bool  ne  = cnt > 0.0f;
            float sum = g_sum[b * C_CH + c];
            float mx  = k2f(g_maxk[b * C_CH + c]);
            pooled_s[i][c]        = ne ? (sum / cnt) : 0.0f;
            pooled_s[i][C_CH + c] = ne ? mx : 0.0f;
            // reset scratch to all-zero identity for the next call
            g_sum [b * C_CH + c] = 0.0f;
            g_maxk[b * C_CH + c] = 0u;
            if (c == 0) g_cnt[b] = 0.0f;
        } else {
            pooled_s[i][c]        = 0.0f;
            pooled_s[i][C_CH + c] = 0.0f;
        }
    }
    __syncthreads();

    // ---- Step B: layer 1 partials. t -> (h = t>>7 k-half, o = t&127).
    //      Thread accumulates both batches over k in [h*128, h*128+128). ----
    {
        const int h = t >> 7;
        const int o = t & 127;
        float a0 = 0.0f, a1 = 0.0f;
        const float* w = W1 + (h * 128) * 128 + o;   // row h*128, col o
        const float* p0 = &pooled_s[0][h * 128];
        const float* p1 = &pooled_s[1][h * 128];
#pragma unroll 16
        for (int k = 0; k < 128; k++) {
            float wv = w[k * 128];                   // coalesced LDG
            a0 += p0[k] * wv;
            a1 += p1[k] * wv;
        }
        p1_s[h][0][o] = a0;
        p1_s[h][1][o] = a1;
    }
    __syncthreads();

    // ---- Step C: combine layer 1 + bias + relu ----
    {
        const int i = t >> 7;
        const int o = t & 127;
        h1_s[i][o] = fmaxf(p1_s[0][i][o] + p1_s[1][i][o] + b1[o], 0.0f);
    }
    __syncthreads();

    // ---- Step D: layer 2 partials. t -> (h = t>>7, i = (t>>6)&1, o = t&63),
    //      k in [h*64, h*64+64). ----
    {
        const int h = t >> 7;
        const int i = (t >> 6) & 1;
        const int o = t & 63;
        float a = 0.0f;
        const float* w  = W2 + (h * 64) * 64 + o;
        const float* hv = &h1_s[i][h * 64];
#pragma unroll 16
        for (int k = 0; k < 64; k++)
            a += hv[k] * w[k * 64];                  // coalesced LDG
        p2_s[h][i][o] = a;
    }
    __syncthreads();

    // ---- Step E: combine layer 2 (threads 0..127) ----
    if (t < 128) {
        const int i = t >> 6;
        const int o = t & 63;
        h2_s[i][o] = fmaxf(p2_s[0][i][o] + p2_s[1][i][o] + b2[o], 0.0f);
    }
    __syncthreads();

    // ---- Step F: layer 3 partials. t -> (h = t>>6 in 0..3, i = (t>>5)&1,
    //      o = t&31), k in [h*16, h*16+16). ----
    {
        const int h = t >> 6;
        const int i = (t >> 5) & 1;
        const int o = t & 31;
        float a = 0.0f;
        const float* w  = W3 + (h * 16) * 32 + o;
        const float* hv = &h2_s[i][h * 16];
#pragma unroll
        for (int k = 0; k < 16; k++)
            a += hv[k] * w[k * 32];                  // coalesced LDG
        p3_s[h][i][o] = a;
    }
    __syncthreads();

    // ---- Step G: combine layer 3 (threads 0..63) ----
    if (t < 64) {
        const int i = t >> 5;
        const int o = t & 31;
        h3_s[i][o] = fmaxf(p3_s[0][i][o] + p3_s[1][i][o] +
                           p3_s[2][i][o] + p3_s[3][i][o] + b3[o], 0.0f);
    }
    __syncthreads();

    // ---- Step H: layer 4 (threads 0..7: i = t>>2, o = t&3) ----
    if (t < 4 * TB) {
        const int i = t >> 2;
        const int o = t & 3;
        float a = b4[o];
#pragma unroll
        for (int k = 0; k < 32; k++)
            a += h3_s[i][k] * W4[k * 4 + o];
        int b = blk_b0 + i;
        if (b < B) out[b * 4 + o] = a;
    }
}

// ---------------------------------------------------------------------------
extern "C" void kernel_launch(void* const* d_in, const int* in_sizes, int n_in,
                              void* d_out, int out_size)
{
    const float* feat = (const float*)d_in[0];
    const int*   bids = (const int*)d_in[1];

    // Inputs (metadata order): features, batch_ids, [batch_size scalar?],
    // W1,b1,W2,b2,W3,b3,W4,b4. Detect whether the scalar batch_size is present.
    int wbase = 2;
    if (n_in >= 11 && in_sizes[2] == 1) wbase = 3;  // skip scalar batch_size

    const float* W1 = (const float*)d_in[wbase + 0];
    const float* b1 = (const float*)d_in[wbase + 1];
    const float* W2 = (const float*)d_in[wbase + 2];
    const float* b2 = (const float*)d_in[wbase + 3];
    const float* W3 = (const float*)d_in[wbase + 4];
    const float* b3 = (const float*)d_in[wbase + 5];
    const float* W4 = (const float*)d_in[wbase + 6];
    const float* b4 = (const float*)d_in[wbase + 7];

    const int N = in_sizes[0] / C_CH;     // rows
    const int B = out_size / 4;           // batch size from output shape

    // 1) segment reduce: 1184 blocks x 8 warps (R2-validated, ~7.9 TB/s).
    {
        int blocks  = 1184;
        int threads = 256;
        int total_warps = blocks * (threads / 32);
        int rpw = (N + total_warps - 1) / total_warps;
        rpw = (rpw + 7) & ~7;   // multiple of 8 so the unrolled loop dominates
        reduce_kernel<<<blocks, threads>>>((const float4*)feat, bids, N, rpw);
    }

    // 2) finalize + MLP head + scratch reset: TB=2 batches per block
    {
        int blocks = (B + TB - 1) / TB;   // 128 for B=256
        head_kernel<<<blocks, 256>>>(W1, b1, W2, b2, W3, b3, W4, b4,
                                     (float*)d_out, B);
    }
}

// round 8
// speedup vs baseline: 1.1213x; 1.0224x over previous
#include <cuda_runtime.h>
#include <math_constants.h>
#include <cfloat>

// ---------------------------------------------------------------------------
// SparseEventNet: segment mean+max pool (N rows, C=128, sorted batch ids)
// followed by a tiny MLP head (2C -> 128 -> 64 -> 32 -> 4).
// Reduce (validated ~7.9 TB/s) + block-0 L2 weight prefetch. Head: stage ALL
// weights into dynamic smem with one batched front load, then split-K compute
// from shared memory. R8 fixes the g_cnt read/reset race (barrier between
// the scratch-read phase and the scratch-reset phase) and removes the static
// attr guard.
// ---------------------------------------------------------------------------

#define C_CH 128
#define B_MAX 1024
#define TB    2      // batches per head block

// Scratch (no cudaMalloc allowed). Module load zero-initializes these, and
// head_kernel restores them to all-zero after consuming them, so every call
// to kernel_launch sees identical (zeroed) scratch. Zero is the identity for
// all three accumulators (sum, offset-encoded max, count).
__device__ float    g_sum[B_MAX * C_CH];
__device__ unsigned g_maxk[B_MAX * C_CH];
__device__ float    g_cnt[B_MAX];

// Monotonic float->uint mapping, offset so that 0 == identity (-FLT_MAX).
__device__ __forceinline__ unsigned f2k_raw(float f) {
    unsigned b = __float_as_uint(f);
    return (b & 0x80000000u) ? ~b : (b | 0x80000000u);
}
// f2k_raw(-FLT_MAX) = ~0xFF7FFFFF = 0x00800000
#define MAXK_BIAS 0x00800000u
__device__ __forceinline__ unsigned f2k(float f) {
    unsigned k = f2k_raw(f);
    return (k <= MAXK_BIAS) ? 0u : (k - MAXK_BIAS);
}
__device__ __forceinline__ float k2f(unsigned k) {
    unsigned raw = k + MAXK_BIAS;
    unsigned b = (raw & 0x80000000u) ? (raw & 0x7FFFFFFFu) : ~raw;
    return __uint_as_float(b);
}

__device__ __forceinline__ void l2_prefetch_range(const void* p, int bytes, int t) {
    const char* c = (const char*)p;
    for (int off = t * 128; off < bytes; off += 256 * 128)
        asm volatile("prefetch.global.L2 [%0];" :: "l"(c + off));
}

// ---------------------------------------------------------------------------
// Segment reduce: one warp owns a contiguous row range. Lane l holds channels
// [4l, 4l+4) in registers (float4). Flush to global atomics only on segment
// change / range end. 8-row unroll, endpoint bids check (ids are sorted).
// Block 0 additionally prefetches the MLP weights into L2 (overlaps with the
// 1 GB stream) so the head's front load is L2-hot.
// ---------------------------------------------------------------------------
__global__ void __launch_bounds__(256) reduce_kernel(
    const float4* __restrict__ feat,   // [N, 32] float4 view of [N, 128]
    const int*    __restrict__ bids,   // [N], sorted
    int N, int rows_per_warp,
    const float* __restrict__ W1, const float* __restrict__ W2,
    const float* __restrict__ W3, const float* __restrict__ W4)
{
    if (blockIdx.x == 0) {
        const int t = threadIdx.x;
        l2_prefetch_range(W1, 256 * 128 * 4, t);
        l2_prefetch_range(W2, 128 * 64 * 4, t);
        l2_prefetch_range(W3, 64 * 32 * 4, t);
        l2_prefetch_range(W4, 32 * 4 * 4, t);
    }

    const int gw   = (blockIdx.x * blockDim.x + threadIdx.x) >> 5;
    const int lane = threadIdx.x & 31;

    int r    = gw * rows_per_warp;
    if (r >= N) return;
    int rend = min(N, r + rows_per_warp);

    int    cur = bids[r];
    float4 s   = make_float4(0.f, 0.f, 0.f, 0.f);
    float4 m   = make_float4(-CUDART_INF_F, -CUDART_INF_F, -CUDART_INF_F, -CUDART_INF_F);
    int    cnt = 0;

#define ACC(v)                                                \
    do {                                                      \
        s.x += (v).x; s.y += (v).y;                           \
        s.z += (v).z; s.w += (v).w;                           \
        m.x = fmaxf(m.x, (v).x); m.y = fmaxf(m.y, (v).y);     \
        m.z = fmaxf(m.z, (v).z); m.w = fmaxf(m.w, (v).w);     \
    } while (0)

#define FLUSH()                                                              \
    do {                                                                     \
        if (cnt > 0) {                                                       \
            float*    sp = &g_sum [cur * C_CH + lane * 4];                   \
            unsigned* mp = &g_maxk[cur * C_CH + lane * 4];                   \
            atomicAdd(sp + 0, s.x); atomicAdd(sp + 1, s.y);                  \
            atomicAdd(sp + 2, s.z); atomicAdd(sp + 3, s.w);                  \
            atomicMax(mp + 0, f2k(m.x)); atomicMax(mp + 1, f2k(m.y));        \
            atomicMax(mp + 2, f2k(m.z)); atomicMax(mp + 3, f2k(m.w));        \
            if (lane == 0) atomicAdd(&g_cnt[cur], (float)cnt);               \
        }                                                                    \
    } while (0)

#define STEP(b, v)                                                           \
    do {                                                                     \
        if ((b) != cur) {                                                    \
            FLUSH();                                                         \
            cur = (b);                                                       \
            s = make_float4(0.f, 0.f, 0.f, 0.f);                             \
            m = make_float4(-CUDART_INF_F, -CUDART_INF_F,                    \
                            -CUDART_INF_F, -CUDART_INF_F);                   \
            cnt = 0;                                                         \
        }                                                                    \
        ACC(v);                                                              \
        cnt++;                                                               \
    } while (0)

    while (r + 8 <= rend) {
        int b0 = bids[r];
        int b7 = bids[r + 7];
        const float4* p = feat + (size_t)r * 32 + lane;
        float4 v0 = __ldcs(p +   0);
        float4 v1 = __ldcs(p +  32);
        float4 v2 = __ldcs(p +  64);
        float4 v3 = __ldcs(p +  96);
        float4 v4 = __ldcs(p + 128);
        float4 v5 = __ldcs(p + 160);
        float4 v6 = __ldcs(p + 192);
        float4 v7 = __ldcs(p + 224);
        if (b0 == cur && b7 == cur) {
            ACC(v0); ACC(v1); ACC(v2); ACC(v3);
            ACC(v4); ACC(v5); ACC(v6); ACC(v7);
            cnt += 8;
        } else {
            int a1 = bids[r + 1], a2 = bids[r + 2], a3 = bids[r + 3];
            int a4 = bids[r + 4], a5 = bids[r + 5], a6 = bids[r + 6];
            STEP(b0, v0); STEP(a1, v1); STEP(a2, v2); STEP(a3, v3);
            STEP(a4, v4); STEP(a5, v5); STEP(a6, v6); STEP(b7, v7);
        }
        r += 8;
    }
    while (r < rend) {
        int    a = bids[r];
        float4 v = __ldcs(feat + (size_t)r * 32 + lane);
        STEP(a, v);
        r++;
    }
    FLUSH();

#undef STEP
#undef FLUSH
#undef ACC
}

// ---------------------------------------------------------------------------
// Head smem layout (floats, dynamic smem). All weights + activations.
// ---------------------------------------------------------------------------
#define W1S_OFF   0          // 32768
#define W2S_OFF   32768      // 8192
#define W3S_OFF   40960      // 2048
#define W4S_OFF   43008      // 128
#define B1S_OFF   43136      // 128
#define B2S_OFF   43264      // 64
#define B3S_OFF   43328      // 32
#define B4S_OFF   43360      // 4 (+4 pad)
#define POOL_OFF  43368      // TB*256 = 512
#define P1_OFF    43880      // 2*TB*128 = 512
#define H1_OFF    44392      // TB*128 = 256
#define P2_OFF    44648      // 2*TB*64 = 256
#define H2_OFF    44904      // TB*64 = 128
#define P3_OFF    45032      // 4*TB*32 = 256
#define H3_OFF    45288      // TB*32 = 64
#define SMEM_FLOATS 45352
#define SMEM_BYTES  (SMEM_FLOATS * 4)

// ---------------------------------------------------------------------------
// Head: finalize pooling + MLP + scratch reset.
// 256 threads per block, TB=2 batches per block, grid = ceil(B/2).
// Phase order: (1) front-load all weights + READ scratch; (2) barrier;
// (3) RESET scratch (no thread can still be reading: the barrier is a
// block-scope memory fence); (4) split-K MLP from shared memory.
// ---------------------------------------------------------------------------
__global__ void __launch_bounds__(256) head_kernel(
    const float* __restrict__ W1, const float* __restrict__ b1,   // [256,128],[128]
    const float* __restrict__ W2, const float* __restrict__ b2,   // [128, 64],[ 64]
    const float* __restrict__ W3, const float* __restrict__ b3,   // [ 64, 32],[ 32]
    const float* __restrict__ W4, const float* __restrict__ b4,   // [ 32,  4],[  4]
    float* __restrict__ out, int B)                               // [B, 4]
{
    extern __shared__ float sm[];
    const int blk_b0 = blockIdx.x * TB;
    const int t      = threadIdx.x;

    float* w1s = sm + W1S_OFF;
    float* w2s = sm + W2S_OFF;
    float* w3s = sm + W3S_OFF;
    float* w4s = sm + W4S_OFF;
    float* b1s = sm + B1S_OFF;
    float* b2s = sm + B2S_OFF;
    float* b3s = sm + B3S_OFF;
    float* b4s = sm + B4S_OFF;
    float* pooled_s = sm + POOL_OFF;   // [TB][256]
    float* p1_s     = sm + P1_OFF;     // [2][TB][128]
    float* h1_s     = sm + H1_OFF;     // [TB][128]
    float* p2_s     = sm + P2_OFF;     // [2][TB][64]
    float* h2_s     = sm + H2_OFF;     // [TB][64]
    float* p3_s     = sm + P3_OFF;     // [4][TB][32]
    float* h3_s     = sm + H3_OFF;     // [TB][32]

    const int fi = t >> 7;         // batch slot 0..1 (finalize mapping)
    const int fc = t & 127;        // channel
    const int fb = blk_b0 + fi;

    // ---- Phase 1a: front load ALL weights + biases (one batched LDG phase)
    {
        const float4* s4;
        float4* d4;
        s4 = (const float4*)W1; d4 = (float4*)w1s;            // 8192 float4
#pragma unroll
        for (int j = 0; j < 32; j++) d4[t + j * 256] = s4[t + j * 256];
        s4 = (const float4*)W2; d4 = (float4*)w2s;            // 2048 float4
#pragma unroll
        for (int j = 0; j < 8; j++) d4[t + j * 256] = s4[t + j * 256];
        s4 = (const float4*)W3; d4 = (float4*)w3s;            // 512 float4
#pragma unroll
        for (int j = 0; j < 2; j++) d4[t + j * 256] = s4[t + j * 256];
        if (t < 32)  ((float4*)w4s)[t] = ((const float4*)W4)[t];
        if (t < 128) b1s[t] = b1[t];
        if (t < 64)  b2s[t] = b2[t];
        if (t < 32)  b3s[t] = b3[t];
        if (t < 4)   b4s[t] = b4[t];
    }

    // ---- Phase 1b: READ scratch, finalize pooling (NO resets here) ----
    {
        float* prow = pooled_s + fi * 256;
        if (fb < B) {
            float cnt = g_cnt[fb];
            bool  ne  = cnt > 0.0f;
            float sum = g_sum[fb * C_CH + fc];
            float mx  = k2f(g_maxk[fb * C_CH + fc]);
            prow[fc]        = ne ? (sum / cnt) : 0.0f;
            prow[C_CH + fc] = ne ? mx : 0.0f;
        } else {
            prow[fc]        = 0.0f;
            prow[C_CH + fc] = 0.0f;
        }
    }
    __syncthreads();   // all scratch READS complete before any reset below

    // ---- Phase 2: RESET scratch to all-zero identity for the next call ----
    if (fb < B) {
        g_sum [fb * C_CH + fc] = 0.0f;
        g_maxk[fb * C_CH + fc] = 0u;
        if (fc == 0) g_cnt[fb] = 0.0f;
    }

    // ---- Layer 1 partials: t -> (h = t>>7 k-half, o = t&127) ----
    {
        const int h = t >> 7;
        const int o = t & 127;
        float a0 = 0.0f, a1 = 0.0f;
        const float* w  = w1s + (h * 128) * 128 + o;
        const float* p0 = pooled_s + 0 * 256 + h * 128;
        const float* p1 = pooled_s + 1 * 256 + h * 128;
#pragma unroll 16
        for (int k = 0; k < 128; k++) {
            float wv = w[k * 128];                   // conflict-free LDS
            a0 += p0[k] * wv;
            a1 += p1[k] * wv;
        }
        p1_s[(h * TB + 0) * 128 + o] = a0;
        p1_s[(h * TB + 1) * 128 + o] = a1;
    }
    __syncthreads();

    // ---- Combine layer 1 + bias + relu ----
    {
        const int i = t >> 7;
        const int o = t & 127;
        h1_s[i * 128 + o] = fmaxf(p1_s[(0 * TB + i) * 128 + o] +
                                  p1_s[(1 * TB + i) * 128 + o] + b1s[o], 0.0f);
    }
    __syncthreads();

    // ---- Layer 2 partials: t -> (h = t>>7, i = (t>>6)&1, o = t&63) ----
    {
        const int h = t >> 7;
        const int i = (t >> 6) & 1;
        const int o = t & 63;
        float a = 0.0f;
        const float* w  = w2s + (h * 64) * 64 + o;
        const float* hv = h1_s + i * 128 + h * 64;
#pragma unroll 16
        for (int k = 0; k < 64; k++)
            a += hv[k] * w[k * 64];
        p2_s[(h * TB + i) * 64 + o] = a;
    }
    __syncthreads();

    // ---- Combine layer 2 (threads 0..127) ----
    if (t < 128) {
        const int i = t >> 6;
        const int o = t & 63;
        h2_s[i * 64 + o] = fmaxf(p2_s[(0 * TB + i) * 64 + o] +
                                 p2_s[(1 * TB + i) * 64 + o] + b2s[o], 0.0f);
    }
    __syncthreads();

    // ---- Layer 3 partials: t -> (h = t>>6 in 0..3, i = (t>>5)&1, o = t&31)
    {
        const int h = t >> 6;
        const int i = (t >> 5) & 1;
        const int o = t & 31;
        float a = 0.0f;
        const float* w  = w3s + (h * 16) * 32 + o;
        const float* hv = h2_s + i * 64 + h * 16;
#pragma unroll
        for (int k = 0; k < 16; k++)
            a += hv[k] * w[k * 32];
        p3_s[(h * TB + i) * 32 + o] = a;
    }
    __syncthreads();

    // ---- Combine layer 3 (threads 0..63) ----
    if (t < 64) {
        const int i = t >> 5;
        const int o = t & 31;
        h3_s[i * 32 + o] = fmaxf(p3_s[(0 * TB + i) * 32 + o] +
                                 p3_s[(1 * TB + i) * 32 + o] +
                                 p3_s[(2 * TB + i) * 32 + o] +
                                 p3_s[(3 * TB + i) * 32 + o] + b3s[o], 0.0f);
    }
    __syncthreads();

    // ---- Layer 4 (threads 0..7: i = t>>2, o = t&3) ----
    if (t < 4 * TB) {
        const int i = t >> 2;
        const int o = t & 3;
        float a = b4s[o];
#pragma unroll
        for (int k = 0; k < 32; k++)
            a += h3_s[i * 32 + k] * w4s[k * 4 + o];
        int b = blk_b0 + i;
        if (b < B) out[b * 4 + o] = a;
    }
}

// ---------------------------------------------------------------------------
extern "C" void kernel_launch(void* const* d_in, const int* in_sizes, int n_in,
                              void* d_out, int out_size)
{
    const float* feat = (const float*)d_in[0];
    const int*   bids = (const int*)d_in[1];

    // Inputs (metadata order): features, batch_ids, [batch_size scalar?],
    // W1,b1,W2,b2,W3,b3,W4,b4. Detect whether the scalar batch_size is present.
    int wbase = 2;
    if (n_in >= 11 && in_sizes[2] == 1) wbase = 3;  // skip scalar batch_size

    const float* W1 = (const float*)d_in[wbase + 0];
    const float* b1 = (const float*)d_in[wbase + 1];
    const float* W2 = (const float*)d_in[wbase + 2];
    const float* b2 = (const float*)d_in[wbase + 3];
    const float* W3 = (const float*)d_in[wbase + 4];
    const float* b3 = (const float*)d_in[wbase + 5];
    const float* W4 = (const float*)d_in[wbase + 6];
    const float* b4 = (const float*)d_in[wbase + 7];

    const int N = in_sizes[0] / C_CH;     // rows
    const int B = out_size / 4;           // batch size from output shape

    // Allow >48KB dynamic smem for the head. Unconditional (no static guards);
    // host-side, idempotent, not a stream operation.
    cudaFuncSetAttribute(head_kernel,
                         cudaFuncAttributeMaxDynamicSharedMemorySize,
                         SMEM_BYTES);

    // 1) segment reduce: 1184 blocks x 8 warps (validated ~7.9 TB/s), with
    //    block-0 L2 prefetch of the head weights.
    {
        int blocks  = 1184;
        int threads = 256;
        int total_warps = blocks * (threads / 32);
        int rpw = (N + total_warps - 1) / total_warps;
        rpw = (rpw + 7) & ~7;   // multiple of 8 so the unrolled loop dominates
        reduce_kernel<<<blocks, threads>>>((const float4*)feat, bids, N, rpw,
                                           W1, W2, W3, W4);
    }

    // 2) finalize + MLP head + scratch reset: TB=2 batches per block
    {
        int blocks = (B + TB - 1) / TB;   // 128 for B=256
        head_kernel<<<blocks, 256, SMEM_BYTES>>>(W1, b1, W2, b2, W3, b3, W4, b4,
                                                 (float*)d_out, B);
    }
}

// round 9
// speedup vs baseline: 1.1521x; 1.0275x over previous
#include <cuda_runtime.h>
#include <math_constants.h>
#include <cfloat>

// ---------------------------------------------------------------------------
// SparseEventNet: segment mean+max pool (N rows, C=128, sorted batch ids)
// followed by a tiny MLP head (2C -> 128 -> 64 -> 32 -> 4).
// Reduce (validated ~7.9 TB/s) + block-0 L2 weight prefetch. Head: all
// weights staged into dynamic smem via cp.async (register-free, unbounded
// pipeline depth), overlapped with the scratch-read finalize phase; then
// split-K compute from shared memory. Scratch read/reset separated by the
// same barrier that completes the cp.async group (R8 race discipline).
// ---------------------------------------------------------------------------

#define C_CH 128
#define B_MAX 1024
#define TB    2      // batches per head block

// Scratch (no cudaMalloc allowed). Module load zero-initializes these, and
// head_kernel restores them to all-zero after consuming them, so every call
// to kernel_launch sees identical (zeroed) scratch. Zero is the identity for
// all three accumulators (sum, offset-encoded max, count).
__device__ float    g_sum[B_MAX * C_CH];
__device__ unsigned g_maxk[B_MAX * C_CH];
__device__ float    g_cnt[B_MAX];

// Monotonic float->uint mapping, offset so that 0 == identity (-FLT_MAX).
__device__ __forceinline__ unsigned f2k_raw(float f) {
    unsigned b = __float_as_uint(f);
    return (b & 0x80000000u) ? ~b : (b | 0x80000000u);
}
// f2k_raw(-FLT_MAX) = ~0xFF7FFFFF = 0x00800000
#define MAXK_BIAS 0x00800000u
__device__ __forceinline__ unsigned f2k(float f) {
    unsigned k = f2k_raw(f);
    return (k <= MAXK_BIAS) ? 0u : (k - MAXK_BIAS);
}
__device__ __forceinline__ float k2f(unsigned k) {
    unsigned raw = k + MAXK_BIAS;
    unsigned b = (raw & 0x80000000u) ? (raw & 0x7FFFFFFFu) : ~raw;
    return __uint_as_float(b);
}

__device__ __forceinline__ void l2_prefetch_range(const void* p, int bytes, int t) {
    const char* c = (const char*)p;
    for (int off = t * 128; off < bytes; off += 256 * 128)
        asm volatile("prefetch.global.L2 [%0];" :: "l"(c + off));
}

__device__ __forceinline__ void cp_async16(float* smem_dst, const float* gsrc) {
    unsigned saddr = (unsigned)__cvta_generic_to_shared(smem_dst);
    asm volatile("cp.async.cg.shared.global [%0], [%1], 16;"
                 :: "r"(saddr), "l"(gsrc) : "memory");
}

// ---------------------------------------------------------------------------
// Segment reduce: one warp owns a contiguous row range. Lane l holds channels
// [4l, 4l+4) in registers (float4). Flush to global atomics only on segment
// change / range end. 8-row unroll, endpoint bids check (ids are sorted).
// Block 0 additionally prefetches the MLP weights into L2 (overlaps with the
// 1 GB stream) so the head's cp.async staging is L2-hot.
// ---------------------------------------------------------------------------
__global__ void __launch_bounds__(256) reduce_kernel(
    const float4* __restrict__ feat,   // [N, 32] float4 view of [N, 128]
    const int*    __restrict__ bids,   // [N], sorted
    int N, int rows_per_warp,
    const float* __restrict__ W1, const float* __restrict__ W2,
    const float* __restrict__ W3, const float* __restrict__ W4)
{
    if (blockIdx.x == 0) {
        const int t = threadIdx.x;
        l2_prefetch_range(W1, 256 * 128 * 4, t);
        l2_prefetch_range(W2, 128 * 64 * 4, t);
        l2_prefetch_range(W3, 64 * 32 * 4, t);
        l2_prefetch_range(W4, 32 * 4 * 4, t);
    }

    const int gw   = (blockIdx.x * blockDim.x + threadIdx.x) >> 5;
    const int lane = threadIdx.x & 31;

    int r    = gw * rows_per_warp;
    if (r >= N) return;
    int rend = min(N, r + rows_per_warp);

    int    cur = bids[r];
    float4 s   = make_float4(0.f, 0.f, 0.f, 0.f);
    float4 m   = make_float4(-CUDART_INF_F, -CUDART_INF_F, -CUDART_INF_F, -CUDART_INF_F);
    int    cnt = 0;

#define ACC(v)                                                \
    do {                                                      \
        s.x += (v).x; s.y += (v).y;                           \
        s.z += (v).z; s.w += (v).w;                           \
        m.x = fmaxf(m.x, (v).x); m.y = fmaxf(m.y, (v).y);     \
        m.z = fmaxf(m.z, (v).z); m.w = fmaxf(m.w, (v).w);     \
    } while (0)

#define FLUSH()                                                              \
    do {                                                                     \
        if (cnt > 0) {                                                       \
            float*    sp = &g_sum [cur * C_CH + lane * 4];                   \
            unsigned* mp = &g_maxk[cur * C_CH + lane * 4];                   \
            atomicAdd(sp + 0, s.x); atomicAdd(sp + 1, s.y);                  \
            atomicAdd(sp + 2, s.z); atomicAdd(sp + 3, s.w);                  \
            atomicMax(mp + 0, f2k(m.x)); atomicMax(mp + 1, f2k(m.y));        \
            atomicMax(mp + 2, f2k(m.z)); atomicMax(mp + 3, f2k(m.w));        \
            if (lane == 0) atomicAdd(&g_cnt[cur], (float)cnt);               \
        }                                                                    \
    } while (0)

#define STEP(b, v)                                                           \
    do {                                                                     \
        if ((b) != cur) {                                                    \
            FLUSH();                                                         \
            cur = (b);                                                       \
            s = make_float4(0.f, 0.f, 0.f, 0.f);                             \
            m = make_float4(-CUDART_INF_F, -CUDART_INF_F,                    \
                            -CUDART_INF_F, -CUDART_INF_F);                   \
            cnt = 0;                                                         \
        }                                                                    \
        ACC(v);                                                              \
        cnt++;                                                               \
    } while (0)

    while (r + 8 <= rend) {
        int b0 = bids[r];
        int b7 = bids[r + 7];
        const float4* p = feat + (size_t)r * 32 + lane;
        float4 v0 = __ldcs(p +   0);
        float4 v1 = __ldcs(p +  32);
        float4 v2 = __ldcs(p +  64);
        float4 v3 = __ldcs(p +  96);
        float4 v4 = __ldcs(p + 128);
        float4 v5 = __ldcs(p + 160);
        float4 v6 = __ldcs(p + 192);
        float4 v7 = __ldcs(p + 224);
        if (b0 == cur && b7 == cur) {
            ACC(v0); ACC(v1); ACC(v2); ACC(v3);
            ACC(v4); ACC(v5); ACC(v6); ACC(v7);
            cnt += 8;
        } else {
            int a1 = bids[r + 1], a2 = bids[r + 2], a3 = bids[r + 3];
            int a4 = bids[r + 4], a5 = bids[r + 5], a6 = bids[r + 6];
            STEP(b0, v0); STEP(a1, v1); STEP(a2, v2); STEP(a3, v3);
            STEP(a4, v4); STEP(a5, v5); STEP(a6, v6); STEP(b7, v7);
        }
        r += 8;
    }
    while (r < rend) {
        int    a = bids[r];
        float4 v = __ldcs(feat + (size_t)r * 32 + lane);
        STEP(a, v);
        r++;
    }
    FLUSH();

#undef STEP
#undef FLUSH
#undef ACC
}

// ---------------------------------------------------------------------------
// Head smem layout (floats, dynamic smem). All weights + activations.
// ---------------------------------------------------------------------------
#define W1S_OFF   0          // 32768
#define W2S_OFF   32768      // 8192
#define W3S_OFF   40960      // 2048
#define W4S_OFF   43008      // 128
#define B1S_OFF   43136      // 128
#define B2S_OFF   43264      // 64
#define B3S_OFF   43328      // 32
#define B4S_OFF   43360      // 4 (+4 pad)
#define POOL_OFF  43368      // TB*256 = 512
#define P1_OFF    43880      // 2*TB*128 = 512
#define H1_OFF    44392      // TB*128 = 256
#define P2_OFF    44648      // 2*TB*64 = 256
#define H2_OFF    44904      // TB*64 = 128
#define P3_OFF    45032      // 4*TB*32 = 256
#define H3_OFF    45288      // TB*32 = 64
#define SMEM_FLOATS 45352
#define SMEM_BYTES  (SMEM_FLOATS * 4)

// ---------------------------------------------------------------------------
// Head: finalize pooling + MLP + scratch reset.
// 256 threads per block, TB=2 batches per block, grid = ceil(B/2).
// Phase order: (1) issue cp.async for ALL weights (register-free, deep
// pipeline) and READ scratch while copies are in flight; (2) cp.async wait +
// barrier (also the read/reset fence); (3) RESET scratch; (4) split-K MLP
// entirely from shared memory.
// ---------------------------------------------------------------------------
__global__ void __launch_bounds__(256) head_kernel(
    const float* __restrict__ W1, const float* __restrict__ b1,   // [256,128],[128]
    const float* __restrict__ W2, const float* __restrict__ b2,   // [128, 64],[ 64]
    const float* __restrict__ W3, const float* __restrict__ b3,   // [ 64, 32],[ 32]
    const float* __restrict__ W4, const float* __restrict__ b4,   // [ 32,  4],[  4]
    float* __restrict__ out, int B)                               // [B, 4]
{
    extern __shared__ float sm[];
    const int blk_b0 = blockIdx.x * TB;
    const int t      = threadIdx.x;

    float* w1s = sm + W1S_OFF;
    float* w2s = sm + W2S_OFF;
    float* w3s = sm + W3S_OFF;
    float* w4s = sm + W4S_OFF;
    float* b1s = sm + B1S_OFF;
    float* b2s = sm + B2S_OFF;
    float* b3s = sm + B3S_OFF;
    float* b4s = sm + B4S_OFF;
    float* pooled_s = sm + POOL_OFF;   // [TB][256]
    float* p1_s     = sm + P1_OFF;     // [2][TB][128]
    float* h1_s     = sm + H1_OFF;     // [TB][128]
    float* p2_s     = sm + P2_OFF;     // [2][TB][64]
    float* h2_s     = sm + H2_OFF;     // [TB][64]
    float* p3_s     = sm + P3_OFF;     // [4][TB][32]
    float* h3_s     = sm + H3_OFF;     // [TB][32]

    const int fi = t >> 7;         // batch slot 0..1 (finalize mapping)
    const int fc = t & 127;        // channel
    const int fb = blk_b0 + fi;

    // ---- Phase 1a: cp.async ALL weights + biases (register-free staging) --
    {
        // W1: 8192 x 16B -> 32 per thread
#pragma unroll
        for (int j = 0; j < 32; j++)
            cp_async16(w1s + (t + j * 256) * 4, W1 + (t + j * 256) * 4);
        // W2: 2048 x 16B -> 8 per thread
#pragma unroll
        for (int j = 0; j < 8; j++)
            cp_async16(w2s + (t + j * 256) * 4, W2 + (t + j * 256) * 4);
        // W3: 512 x 16B -> 2 per thread
#pragma unroll
        for (int j = 0; j < 2; j++)
            cp_async16(w3s + (t + j * 256) * 4, W3 + (t + j * 256) * 4);
        // W4: 32 x 16B
        if (t < 32) cp_async16(w4s + t * 4, W4 + t * 4);
        // biases: b1 32x16B, b2 16x16B, b3 8x16B, b4 1x16B
        if (t < 32) cp_async16(b1s + t * 4, b1 + t * 4);
        if (t < 16) cp_async16(b2s + t * 4, b2 + t * 4);
        if (t < 8)  cp_async16(b3s + t * 4, b3 + t * 4);
        if (t < 1)  cp_async16(b4s + t * 4, b4 + t * 4);
        asm volatile("cp.async.commit_group;" ::: "memory");
    }

    // ---- Phase 1b: READ scratch, finalize pooling (overlaps cp.async) ----
    {
        float* prow = pooled_s + fi * 256;
        if (fb < B) {
            float cnt = g_cnt[fb];
            bool  ne  = cnt > 0.0f;
            float sum = g_sum[fb * C_CH + fc];
            float mx  = k2f(g_maxk[fb * C_CH + fc]);
            prow[fc]        = ne ? (sum / cnt) : 0.0f;
            prow[C_CH + fc] = ne ? mx : 0.0f;
        } else {
            prow[fc]        = 0.0f;
            prow[C_CH + fc] = 0.0f;
        }
    }
    asm volatile("cp.async.wait_group 0;" ::: "memory");
    __syncthreads();   // copies visible; all scratch READS done before resets

    // ---- Phase 2: RESET scratch to all-zero identity for the next call ----
    if (fb < B) {
        g_sum [fb * C_CH + fc] = 0.0f;
        g_maxk[fb * C_CH + fc] = 0u;
        if (fc == 0) g_cnt[fb] = 0.0f;
    }

    // ---- Layer 1 partials: t -> (h = t>>7 k-half, o = t&127) ----
    {
        const int h = t >> 7;
        const int o = t & 127;
        float a0 = 0.0f, a1 = 0.0f;
        const float* w  = w1s + (h * 128) * 128 + o;
        const float* p0 = pooled_s + 0 * 256 + h * 128;
        const float* p1 = pooled_s + 1 * 256 + h * 128;
#pragma unroll 16
        for (int k = 0; k < 128; k++) {
            float wv = w[k * 128];                   // conflict-free LDS
            a0 += p0[k] * wv;
            a1 += p1[k] * wv;
        }
        p1_s[(h * TB + 0) * 128 + o] = a0;
        p1_s[(h * TB + 1) * 128 + o] = a1;
    }
    __syncthreads();

    // ---- Combine layer 1 + bias + relu ----
    {
        const int i = t >> 7;
        const int o = t & 127;
        h1_s[i * 128 + o] = fmaxf(p1_s[(0 * TB + i) * 128 + o] +
                                  p1_s[(1 * TB + i) * 128 + o] + b1s[o], 0.0f);
    }
    __syncthreads();

    // ---- Layer 2 partials: t -> (h = t>>7, i = (t>>6)&1, o = t&63) ----
    {
        const int h = t >> 7;
        const int i = (t >> 6) & 1;
        const int o = t & 63;
        float a = 0.0f;
        const float* w  = w2s + (h * 64) * 64 + o;
        const float* hv = h1_s + i * 128 + h * 64;
#pragma unroll 16
        for (int k = 0; k < 64; k++)
            a += hv[k] * w[k * 64];
        p2_s[(h * TB + i) * 64 + o] = a;
    }
    __syncthreads();

    // ---- Combine layer 2 (threads 0..127) ----
    if (t < 128) {
        const int i = t >> 6;
        const int o = t & 63;
        h2_s[i * 64 + o] = fmaxf(p2_s[(0 * TB + i) * 64 + o] +
                                 p2_s[(1 * TB + i) * 64 + o] + b2s[o], 0.0f);
    }
    __syncthreads();

    // ---- Layer 3 partials: t -> (h = t>>6 in 0..3, i = (t>>5)&1, o = t&31)
    {
        const int h = t >> 6;
        const int i = (t >> 5) & 1;
        const int o = t & 31;
        float a = 0.0f;
        const float* w  = w3s + (h * 16) * 32 + o;
        const float* hv = h2_s + i * 64 + h * 16;
#pragma unroll
        for (int k = 0; k < 16; k++)
            a += hv[k] * w[k * 32];
        p3_s[(h * TB + i) * 32 + o] = a;
    }
    __syncthreads();

    // ---- Combine layer 3 (threads 0..63) ----
    if (t < 64) {
        const int i = t >> 5;
        const int o = t & 31;
        h3_s[i * 32 + o] = fmaxf(p3_s[(0 * TB + i) * 32 + o] +
                                 p3_s[(1 * TB + i) * 32 + o] +
                                 p3_s[(2 * TB + i) * 32 + o] +
                                 p3_s[(3 * TB + i) * 32 + o] + b3s[o], 0.0f);
    }
    __syncthreads();

    // ---- Layer 4 (threads 0..7: i = t>>2, o = t&3) ----
    if (t < 4 * TB) {
        const int i = t >> 2;
        const int o = t & 3;
        float a = b4s[o];
#pragma unroll
        for (int k = 0; k < 32; k++)
            a += h3_s[i * 32 + k] * w4s[k * 4 + o];
        int b = blk_b0 + i;
        if (b < B) out[b * 4 + o] = a;
    }
}

// ---------------------------------------------------------------------------
extern "C" void kernel_launch(void* const* d_in, const int* in_sizes, int n_in,
                              void* d_out, int out_size)
{
    const float* feat = (const float*)d_in[0];
    const int*   bids = (const int*)d_in[1];

    // Inputs (metadata order): features, batch_ids, [batch_size scalar?],
    // W1,b1,W2,b2,W3,b3,W4,b4. Detect whether the scalar batch_size is present.
    int wbase = 2;
    if (n_in >= 11 && in_sizes[2] == 1) wbase = 3;  // skip scalar batch_size

    const float* W1 = (const float*)d_in[wbase + 0];
    const float* b1 = (const float*)d_in[wbase + 1];
    const float* W2 = (const float*)d_in[wbase + 2];
    const float* b2 = (const float*)d_in[wbase + 3];
    const float* W3 = (const float*)d_in[wbase + 4];
    const float* b3 = (const float*)d_in[wbase + 5];
    const float* W4 = (const float*)d_in[wbase + 6];
    const float* b4 = (const float*)d_in[wbase + 7];

    const int N = in_sizes[0] / C_CH;     // rows
    const int B = out_size / 4;           // batch size from output shape

    // Allow >48KB dynamic smem for the head. Unconditional (no static guards);
    // host-side, idempotent, not a stream operation.
    cudaFuncSetAttribute(head_kernel,
                         cudaFuncAttributeMaxDynamicSharedMemorySize,
                         SMEM_BYTES);

    // 1) segment reduce: 1184 blocks x 8 warps (validated ~7.9 TB/s), with
    //    block-0 L2 prefetch of the head weights.
    {
        int blocks  = 1184;
        int threads = 256;
        int total_warps = blocks * (threads / 32);
        int rpw = (N + total_warps - 1) / total_warps;
        rpw = (rpw + 7) & ~7;   // multiple of 8 so the unrolled loop dominates
        reduce_kernel<<<blocks, threads>>>((const float4*)feat, bids, N, rpw,
                                           W1, W2, W3, W4);
    }

    // 2) finalize + MLP head + scratch reset: TB=2 batches per block
    {
        int blocks = (B + TB - 1) / TB;   // 128 for B=256
        head_kernel<<<blocks, 256, SMEM_BYTES>>>(W1, b1, W2, b2, W3, b3, W4, b4,
                                                 (float*)d_out, B);
    }
}